// round 9
// baseline (speedup 1.0000x reference)
#include <cuda_runtime.h>

// Equivariant linear: RS = [(16,0),(16,1),(16,2)], dim = 144, BATCH = 262144.
// Block-diagonal per (l,m): out[z,l,v,t] = sum_u Wl[v,u] * x[z,l,u,t],
// Wl[v,u] = weight[l*256 + v*16 + u] * 0.25 / sqrt(2l+1).
// Row layout: l=0 cols [0,16) d=1; l=1 idx 16+u*3+t; l=2 idx 64+u*5+t.
//
// R9: W in __constant__ (LDC port, off the L1 pipe). 64-row tiles, 288 thr
// (9 warps = 9 slices), 2 rows/thread, v-outer matvec with u-paired f32x2.

#define ROWS 64
#define STRIDE 145      // odd -> row-axis scalar gather/scatter conflict-free
#define NT 288          // 9 warps = 9 m-slices
#define DIM 144
#define EPT 32          // 64*144 / 288 staged elements per thread

typedef unsigned long long ull;

__constant__ __align__(16) float cW[768];   // raw weights, W[l][v][u]

__device__ __forceinline__ ull pack_dup(float x) {
    ull r;
    asm("mov.b64 %0, {%1, %1};" : "=l"(r) : "f"(x));
    return r;
}
__device__ __forceinline__ ull pack2(float lo, float hi) {
    ull r;
    asm("mov.b64 %0, {%1, %2};" : "=l"(r) : "f"(lo), "f"(hi));
    return r;
}
__device__ __forceinline__ ull mul2(ull a, ull b) {
    ull r;
    asm("mul.rn.f32x2 %0, %1, %2;" : "=l"(r) : "l"(a), "l"(b));
    return r;
}
__device__ __forceinline__ void ffma2(ull& acc, ull w2, ull x2) {
    asm("fma.rn.f32x2 %0, %1, %2, %0;" : "+l"(acc) : "l"(w2), "l"(x2));
}
__device__ __forceinline__ float hadd2(ull p) {
    float lo, hi;
    asm("mov.b64 {%0, %1}, %2;" : "=f"(lo), "=f"(hi) : "l"(p));
    return lo + hi;
}

__global__ __launch_bounds__(NT) void eq_linear_kernel(
    const float* __restrict__ x,
    float* __restrict__ y)
{
    __shared__ float sD[ROWS * STRIDE];

    const int tid  = threadIdx.x;
    const int lane = tid & 31;
    const int s    = tid >> 5;      // warp id == slice id, 0..8

    const long long row0 = (long long)blockIdx.x * ROWS;

    // Coalesced scalar tile load: thread owns column c = tid % 144,
    // rows rb + 2k; consecutive lanes -> consecutive addresses, STS
    // conflict-free (1 wf each).
    const int c  = tid % DIM;
    const int rb = tid / DIM;       // 0 or 1
    {
        const float* __restrict__ gsrc = x + (row0 + rb) * DIM + c;
        float* ssrc = sD + rb * STRIDE + c;
        #pragma unroll
        for (int k = 0; k < EPT; k++)
            ssrc[(2 * k) * STRIDE] = gsrc[(long long)(2 * k) * DIM];
    }
    __syncthreads();

    // Slice geometry.
    int l, off, d;
    float scale;
    if (s == 0)      { l = 0; off = 0;            d = 1; scale = 0.25f; }
    else if (s < 4)  { l = 1; off = 16 + (s - 1); d = 3;
                       scale = 0.25f * 0.57735026918962576f; }   // 1/sqrt(3)
    else             { l = 2; off = 64 + (s - 4); d = 5;
                       scale = 0.25f * 0.44721359549995794f; }   // 1/sqrt(5)

    // Compute: warp s owns slice s; lane owns rows {lane, lane+32}.
    {
        float* p0 = sD + lane * STRIDE + off;
        float* p1 = p0 + 32 * STRIDE;
        const ull sc2 = pack_dup(scale);

        // Gather + pack + scale the 16 inputs of each row (u-paired).
        ull x0[8], x1[8];
        #pragma unroll
        for (int up = 0; up < 8; up++) {
            x0[up] = mul2(pack2(p0[(2*up) * d], p0[(2*up+1) * d]), sc2);
            x1[up] = mul2(pack2(p1[(2*up) * d], p1[(2*up+1) * d]), sc2);
        }

        // v-outer matvec; W row W[l][v][0..15] is contiguous -> LDC.128 x4.
        const ulonglong2* __restrict__ w2 =
            reinterpret_cast<const ulonglong2*>(cW + l * 256);
        #pragma unroll
        for (int v = 0; v < 16; v++) {
            ulonglong2 wa = w2[v * 4 + 0];   // {w0,w1},{w2,w3}
            ulonglong2 wb = w2[v * 4 + 1];   // {w4,w5},{w6,w7}
            ulonglong2 wc = w2[v * 4 + 2];
            ulonglong2 wd = w2[v * 4 + 3];

            ull a0 = 0ull, a1 = 0ull;
            ffma2(a0, wa.x, x0[0]); ffma2(a1, wa.x, x1[0]);
            ffma2(a0, wa.y, x0[1]); ffma2(a1, wa.y, x1[1]);
            ffma2(a0, wb.x, x0[2]); ffma2(a1, wb.x, x1[2]);
            ffma2(a0, wb.y, x0[3]); ffma2(a1, wb.y, x1[3]);
            ffma2(a0, wc.x, x0[4]); ffma2(a1, wc.x, x1[4]);
            ffma2(a0, wc.y, x0[5]); ffma2(a1, wc.y, x1[5]);
            ffma2(a0, wd.x, x0[6]); ffma2(a1, wd.x, x1[6]);
            ffma2(a0, wd.y, x0[7]); ffma2(a1, wd.y, x1[7]);

            p0[v * d] = hadd2(a0);           // conflict-free scalar STS
            p1[v * d] = hadd2(a1);
        }
    }
    __syncthreads();

    // Coalesced scalar store (mirror of the load).
    {
        float* __restrict__ gdst = y + (row0 + rb) * DIM + c;
        const float* sdst = sD + rb * STRIDE + c;
        #pragma unroll
        for (int k = 0; k < EPT; k++)
            gdst[(long long)(2 * k) * DIM] = sdst[(2 * k) * STRIDE];
    }
}

extern "C" void kernel_launch(void* const* d_in, const int* in_sizes, int n_in,
                              void* d_out, int out_size)
{
    const float* feat = (const float*)d_in[0];
    const float* w    = (const float*)d_in[1];
    float* out        = (float*)d_out;

    // Raw weights -> constant bank (D2D async memcpy node; graph-capturable).
    cudaMemcpyToSymbolAsync(cW, w, 768 * sizeof(float), 0,
                            cudaMemcpyDeviceToDevice, 0);

    const int batch  = in_sizes[0] / DIM;   // 262144
    const int blocks = batch / ROWS;        // 4096

    eq_linear_kernel<<<blocks, NT>>>(feat, out);
}

// round 10
// speedup vs baseline: 1.0086x; 1.0086x over previous
#include <cuda_runtime.h>

// Equivariant linear: RS = [(16,0),(16,1),(16,2)], dim = 144, BATCH = 262144.
// Block-diagonal per (l,m): out[z,l,v,t] = sum_u Wl[v,u] * x[z,l,u,t],
// Wl[v,u] = weight[l*256 + v*16 + u] * 0.25 / sqrt(2l+1).
// Row layout: l=0 cols [0,16) d=1; l=1 idx 16+u*3+t; l=2 idx 64+u*5+t.
//
// R10: 96-thread CTAs (3 warps x 3 slices), 32-row tiles, ~12 CTAs/SM so
// load/compute/store phases of many CTAs interleave and keep DRAM busy.
// W stays in __constant__ (LDC port, off the L1 pipe).

#define ROWS 32
#define STRIDE 145      // odd -> row-axis scalar gather/scatter conflict-free
#define NT 96           // 3 warps; warp w handles slices {w, w+3, w+6}
#define DIM 144
#define EPT 48          // 32*144 / 96 staged elements per thread

typedef unsigned long long ull;

__constant__ __align__(16) float cW[768];   // raw weights, W[l][v][u]

__device__ __forceinline__ ull pack_dup(float x) {
    ull r;
    asm("mov.b64 %0, {%1, %1};" : "=l"(r) : "f"(x));
    return r;
}
__device__ __forceinline__ ull pack2(float lo, float hi) {
    ull r;
    asm("mov.b64 %0, {%1, %2};" : "=l"(r) : "f"(lo), "f"(hi));
    return r;
}
__device__ __forceinline__ ull mul2(ull a, ull b) {
    ull r;
    asm("mul.rn.f32x2 %0, %1, %2;" : "=l"(r) : "l"(a), "l"(b));
    return r;
}
__device__ __forceinline__ void ffma2(ull& acc, ull w2, ull x2) {
    asm("fma.rn.f32x2 %0, %1, %2, %0;" : "+l"(acc) : "l"(w2), "l"(x2));
}
__device__ __forceinline__ float hadd2(ull p) {
    float lo, hi;
    asm("mov.b64 {%0, %1}, %2;" : "=f"(lo), "=f"(hi) : "l"(p));
    return lo + hi;
}

__global__ __launch_bounds__(NT) void eq_linear_kernel(
    const float* __restrict__ x,
    float* __restrict__ y)
{
    __shared__ float sD[ROWS * STRIDE];

    const int tid  = threadIdx.x;
    const int lane = tid & 31;
    const int wrp  = tid >> 5;      // 0..2

    const long long row0 = (long long)blockIdx.x * ROWS;

    // Coalesced scalar tile load: i = tid + 96k; r = i/144, c = i%144.
    // Consecutive lanes -> consecutive addresses (LDG 1 wf, STS conflict-free).
    {
        const float* __restrict__ gbase = x + row0 * DIM;
        #pragma unroll
        for (int k = 0; k < EPT; k++) {
            int i = tid + k * NT;
            int r = i / DIM;
            int c = i % DIM;
            sD[r * STRIDE + c] = gbase[i];
        }
    }
    __syncthreads();

    // Compute: warp wrp handles slices {wrp, wrp+3, wrp+6}; lane owns row lane.
    #pragma unroll
    for (int si = 0; si < 3; si++) {
        const int s = wrp + si * 3;

        int l, off, d;
        float scale;
        if (s == 0)      { l = 0; off = 0;            d = 1; scale = 0.25f; }
        else if (s < 4)  { l = 1; off = 16 + (s - 1); d = 3;
                           scale = 0.25f * 0.57735026918962576f; }  // 1/sqrt(3)
        else             { l = 2; off = 64 + (s - 4); d = 5;
                           scale = 0.25f * 0.44721359549995794f; }  // 1/sqrt(5)

        float* p = sD + lane * STRIDE + off;
        const ull sc2 = pack_dup(scale);

        // Gather + pack + scale the 16 inputs (u-paired f32x2).
        ull xr[8];
        #pragma unroll
        for (int up = 0; up < 8; up++)
            xr[up] = mul2(pack2(p[(2*up) * d], p[(2*up+1) * d]), sc2);

        // v-outer matvec; W row W[l][v][0..15] contiguous -> LDC.128 x4,
        // warp-uniform on the constant port (off the L1/smem pipe).
        const ulonglong2* __restrict__ w2 =
            reinterpret_cast<const ulonglong2*>(cW + l * 256);
        #pragma unroll
        for (int v = 0; v < 16; v++) {
            ulonglong2 wa = w2[v * 4 + 0];
            ulonglong2 wb = w2[v * 4 + 1];
            ulonglong2 wc = w2[v * 4 + 2];
            ulonglong2 wd = w2[v * 4 + 3];

            ull a = 0ull;
            ffma2(a, wa.x, xr[0]);
            ffma2(a, wa.y, xr[1]);
            ffma2(a, wb.x, xr[2]);
            ffma2(a, wb.y, xr[3]);
            ffma2(a, wc.x, xr[4]);
            ffma2(a, wc.y, xr[5]);
            ffma2(a, wd.x, xr[6]);
            ffma2(a, wd.y, xr[7]);

            p[v * d] = hadd2(a);       // conflict-free scalar STS
        }
    }
    __syncthreads();

    // Coalesced scalar store (mirror of the load).
    {
        float* __restrict__ gbase = y + row0 * DIM;
        #pragma unroll
        for (int k = 0; k < EPT; k++) {
            int i = tid + k * NT;
            int r = i / DIM;
            int c = i % DIM;
            gbase[i] = sD[r * STRIDE + c];
        }
    }
}

extern "C" void kernel_launch(void* const* d_in, const int* in_sizes, int n_in,
                              void* d_out, int out_size)
{
    const float* feat = (const float*)d_in[0];
    const float* w    = (const float*)d_in[1];
    float* out        = (float*)d_out;

    // Raw weights -> constant bank (D2D async memcpy node; graph-capturable).
    cudaMemcpyToSymbolAsync(cW, w, 768 * sizeof(float), 0,
                            cudaMemcpyDeviceToDevice, 0);

    const int batch  = in_sizes[0] / DIM;   // 262144
    const int blocks = batch / ROWS;        // 8192

    eq_linear_kernel<<<blocks, NT>>>(feat, out);
}